// round 7
// baseline (speedup 1.0000x reference)
#include <cuda_runtime.h>
#include <cstdint>

// Problem constants
#define NN   50000
#define EE   800000
#define FE   16
#define RR   4
#define HH   4
#define CC   32
#define HC   128

// ---------------- scratch (static device globals; no allocation) ----------------
__device__ __align__(16) float g_xw[RR * NN * HC];   // per-relation projections (102.4MB)
__device__ __align__(16) float g_h[NN * HC];         // layer-1 output (relu)
__device__ __align__(16) float g_qn[RR * NN * HH];   // per-node query logits [r][n][4]
__device__ __align__(16) float g_kn[RR * NN * HH];   // per-node key logits   [r][n][4]
__device__ __align__(16) float4 g_pp[EE];            // per-edge probs, CSR-permuted
__device__ int   g_deg[NN];
__device__ int   g_rowstart[NN + 1];
__device__ int   g_cursor[NN];
__device__ int   g_csr32[EE];                        // (et<<16)|src, sorted by dst
__device__ int   g_pos[EE];                          // edge id -> csr position
__device__ float g_M1[FE * HH];
__device__ float g_M3[FE * HH];
// W pre-fragmented for mma.m16n8k8 tf32: [r][phase p(4)][s(4)][ntile j(16)][lane(32)][2]
__device__ __align__(16) uint32_t g_wf[RR * 4 * 4 * 16 * 32 * 2];

__device__ __forceinline__ uint32_t f2tf32(float f) {
    uint32_t u;
    asm("cvt.rna.tf32.f32 %0, %1;" : "=r"(u) : "f"(f));
    return u;
}

// ---------------- CSR build ----------------
__global__ void k_zero_deg() {
    int i = blockIdx.x * blockDim.x + threadIdx.x;
    if (i < NN) g_deg[i] = 0;
}

__global__ void k_hist(const int* __restrict__ ei) {
    int e = blockIdx.x * blockDim.x + threadIdx.x;
    if (e < EE) atomicAdd(&g_deg[ei[EE + e]], 1);
}

// single-block exclusive scan of g_deg -> g_rowstart / g_cursor
__global__ void k_scan() {
    __shared__ int sm[1024];
    __shared__ int s_carry;
    int tid = threadIdx.x;
    if (tid == 0) s_carry = 0;
    __syncthreads();
    const int TILES = (NN + 8191) / 8192;   // 7
    for (int tile = 0; tile < TILES; tile++) {
        int base = tile * 8192 + tid * 8;
        int v[8];
        int tsum = 0;
#pragma unroll
        for (int j = 0; j < 8; j++) {
            int idx = base + j;
            v[j] = (idx < NN) ? g_deg[idx] : 0;
            tsum += v[j];
        }
        sm[tid] = tsum;
        __syncthreads();
        for (int off = 1; off < 1024; off <<= 1) {
            int t = (tid >= off) ? sm[tid - off] : 0;
            __syncthreads();
            sm[tid] += t;
            __syncthreads();
        }
        int excl = s_carry + sm[tid] - tsum;
        int run = excl;
#pragma unroll
        for (int j = 0; j < 8; j++) {
            int idx = base + j;
            if (idx < NN) { g_rowstart[idx] = run; g_cursor[idx] = run; }
            run += v[j];
        }
        __syncthreads();
        if (tid == 0) s_carry += sm[1023];
        __syncthreads();
    }
    if (tid == 0) g_rowstart[NN] = s_carry;
}

__global__ void k_scatter(const int* __restrict__ ei, const int* __restrict__ etype) {
    int e = blockIdx.x * blockDim.x + threadIdx.x;
    if (e >= EE) return;
    int d = ei[EE + e];
    int s = ei[e];
    int t = etype[e];
    int pos = atomicAdd(&g_cursor[d], 1);
    g_csr32[pos] = (t << 16) | s;
    g_pos[e] = pos;
}

// ---------------- W fragment pack for mma.m16n8k8 tf32 ----------------
__global__ void k_wfrag(const float* __restrict__ w) {
    int idx = blockIdx.x * 256 + threadIdx.x;          // over 65536
    if (idx >= RR * 4 * 4 * 16 * 32 * 2) return;
    int b    = idx & 1;
    int lane = (idx >> 1) & 31;
    int j    = (idx >> 6) & 15;
    int s    = (idx >> 10) & 3;
    int p    = (idx >> 12) & 3;
    int r    = idx >> 14;
    int k = p * 32 + s * 8 + (b ? 4 : 0) + (lane & 3);
    int c = j * 8 + (lane >> 2);
    g_wf[idx] = f2tf32(w[((size_t)r << 14) + k * 128 + c]);
}

// ---------------- M = le @ e  (16x4, both layers) ----------------
__global__ void k_M(const float* __restrict__ le1, const float* __restrict__ e1,
                    const float* __restrict__ le3, const float* __restrict__ e3) {
    int t = threadIdx.x;
    if (t < 64) {
        int f = t >> 2, h = t & 3;
        float s = 0.f;
        for (int c = 0; c < HC; c++) s += le1[f * HC + c] * e1[c * HH + h];
        g_M1[t] = s;
    } else if (t < 128) {
        int u = t - 64;
        int f = u >> 2, h = u & 3;
        float s = 0.f;
        for (int c = 0; c < HC; c++) s += le3[f * HC + c] * e3[c * HH + h];
        g_M3[u] = s;
    }
}

// ---------------- tensor-core GEMM + fused q/k epilogue ----------------
// xw[r] = X @ W[r] (tf32 mma, fp32 accum); also qn/kn[r][row] = xw_row @ q/k
// computed from accumulator fragments + quad-shfl reduction.
#define XS_STRIDE 36
__global__ void __launch_bounds__(256) k_gemmt(const float* __restrict__ xin_arg,
                                               const float* __restrict__ qm,
                                               const float* __restrict__ km,
                                               int layer) {
    __shared__ uint32_t xs[128 * XS_STRIDE];           // 18.4 KB (tf32 bits)
    __shared__ uint32_t ws[4 * 16 * 32 * 2];           // 16 KB per K-phase
    __shared__ __align__(16) float sqk[128 * 8];       // 4 KB: [c][q0..3 k0..3]
    const float* xin = (layer == 1) ? xin_arg : g_h;
    int r = blockIdx.y;
    int i0 = blockIdx.x * 128;
    int tid = threadIdx.x;
    int lane = tid & 31, wid = tid >> 5;
    int wr = wid * 16;                                  // warp row offset

    // load q|k table
#pragma unroll
    for (int it = 0; it < 4; it++) {
        int idx = tid + it * 256;                       // 1024
        int c = idx >> 3, o = idx & 7;
        sqk[idx] = (o < 4) ? qm[c * 4 + o] : km[c * 4 + (o - 4)];
    }

    float d[16][4];
#pragma unroll
    for (int j = 0; j < 16; j++) {
        d[j][0] = 0.f; d[j][1] = 0.f; d[j][2] = 0.f; d[j][3] = 0.f;
    }

    const uint32_t* wsrc = g_wf + (size_t)r * 16384;

    for (int p = 0; p < 4; p++) {
        __syncthreads();                                // protect prev phase reads
#pragma unroll
        for (int it = 0; it < 4; it++) {
            int q = tid + it * 256;                     // float4 index
            int row = q >> 3, c4 = q & 7;
            float4 v = make_float4(0.f, 0.f, 0.f, 0.f);
            int gr = i0 + row;
            if (gr < NN) v = *(const float4*)(xin + (size_t)gr * 128 + p * 32 + c4 * 4);
            uint32_t* dst = &xs[row * XS_STRIDE + c4 * 4];
            dst[0] = f2tf32(v.x); dst[1] = f2tf32(v.y);
            dst[2] = f2tf32(v.z); dst[3] = f2tf32(v.w);
        }
        const uint4* wsp = (const uint4*)(wsrc + p * 4096);
#pragma unroll
        for (int it = 0; it < 4; it++) {
            int q = tid + it * 256;
            ((uint4*)ws)[q] = __ldg(&wsp[q]);
        }
        __syncthreads();

#pragma unroll
        for (int s = 0; s < 4; s++) {
            int arow = wr + (lane >> 2);
            int acol = s * 8 + (lane & 3);
            uint32_t a0 = xs[arow * XS_STRIDE + acol];
            uint32_t a1 = xs[(arow + 8) * XS_STRIDE + acol];
            uint32_t a2 = xs[arow * XS_STRIDE + acol + 4];
            uint32_t a3 = xs[(arow + 8) * XS_STRIDE + acol + 4];
            const uint32_t* wrow = &ws[(s * 16) * 64];
#pragma unroll
            for (int j = 0; j < 16; j++) {
                uint2 bv = *(const uint2*)&wrow[j * 64 + lane * 2];
                asm volatile(
                    "mma.sync.aligned.m16n8k8.row.col.f32.tf32.tf32.f32 "
                    "{%0,%1,%2,%3}, {%4,%5,%6,%7}, {%8,%9}, {%0,%1,%2,%3};"
                    : "+f"(d[j][0]), "+f"(d[j][1]), "+f"(d[j][2]), "+f"(d[j][3])
                    : "r"(a0), "r"(a1), "r"(a2), "r"(a3), "r"(bv.x), "r"(bv.y));
            }
        }
    }

    // store xw tile
    int row0 = i0 + wr + (lane >> 2);
    int row1 = row0 + 8;
    float* base = g_xw + (size_t)r * NN * HC;
#pragma unroll
    for (int j = 0; j < 16; j++) {
        int col = j * 8 + (lane & 3) * 2;
        if (row0 < NN) *(float2*)&base[(size_t)row0 * 128 + col] = make_float2(d[j][0], d[j][1]);
        if (row1 < NN) *(float2*)&base[(size_t)row1 * 128 + col] = make_float2(d[j][2], d[j][3]);
    }

    // fused q/k epilogue: per-row dot with q|k table, quad reduce
    float qk0[8], qk1[8];
#pragma unroll
    for (int o = 0; o < 8; o++) { qk0[o] = 0.f; qk1[o] = 0.f; }
#pragma unroll
    for (int j = 0; j < 16; j++) {
        int c0 = j * 8 + (lane & 3) * 2;
        float4 qa = *(const float4*)&sqk[c0 * 8];
        float4 ka = *(const float4*)&sqk[c0 * 8 + 4];
        float4 qb = *(const float4*)&sqk[(c0 + 1) * 8];
        float4 kb = *(const float4*)&sqk[(c0 + 1) * 8 + 4];
        qk0[0] += d[j][0] * qa.x + d[j][1] * qb.x;
        qk0[1] += d[j][0] * qa.y + d[j][1] * qb.y;
        qk0[2] += d[j][0] * qa.z + d[j][1] * qb.z;
        qk0[3] += d[j][0] * qa.w + d[j][1] * qb.w;
        qk0[4] += d[j][0] * ka.x + d[j][1] * kb.x;
        qk0[5] += d[j][0] * ka.y + d[j][1] * kb.y;
        qk0[6] += d[j][0] * ka.z + d[j][1] * kb.z;
        qk0[7] += d[j][0] * ka.w + d[j][1] * kb.w;
        qk1[0] += d[j][2] * qa.x + d[j][3] * qb.x;
        qk1[1] += d[j][2] * qa.y + d[j][3] * qb.y;
        qk1[2] += d[j][2] * qa.z + d[j][3] * qb.z;
        qk1[3] += d[j][2] * qa.w + d[j][3] * qb.w;
        qk1[4] += d[j][2] * ka.x + d[j][3] * kb.x;
        qk1[5] += d[j][2] * ka.y + d[j][3] * kb.y;
        qk1[6] += d[j][2] * ka.z + d[j][3] * kb.z;
        qk1[7] += d[j][2] * ka.w + d[j][3] * kb.w;
    }
#pragma unroll
    for (int o = 0; o < 8; o++) {
        qk0[o] += __shfl_xor_sync(0xFFFFFFFF, qk0[o], 1);
        qk0[o] += __shfl_xor_sync(0xFFFFFFFF, qk0[o], 2);
        qk1[o] += __shfl_xor_sync(0xFFFFFFFF, qk1[o], 1);
        qk1[o] += __shfl_xor_sync(0xFFFFFFFF, qk1[o], 2);
    }
    if ((lane & 3) == 0) {
        if (row0 < NN) {
            *(float4*)&g_qn[((size_t)r * NN + row0) * 4] = make_float4(qk0[0], qk0[1], qk0[2], qk0[3]);
            *(float4*)&g_kn[((size_t)r * NN + row0) * 4] = make_float4(qk0[4], qk0[5], qk0[6], qk0[7]);
        }
        if (row1 < NN) {
            *(float4*)&g_qn[((size_t)r * NN + row1) * 4] = make_float4(qk1[0], qk1[1], qk1[2], qk1[3]);
            *(float4*)&g_kn[((size_t)r * NN + row1) * 4] = make_float4(qk1[4], qk1[5], qk1[6], qk1[7]);
        }
    }
}

// ---------------- per-edge probs, written in CSR order ----------------
__global__ void k_p(const int* __restrict__ ei, const int* __restrict__ etype,
                    const float* __restrict__ eattr, int layer) {
    __shared__ float sM[64];
    if (threadIdx.x < 64) sM[threadIdx.x] = (layer == 1) ? g_M1[threadIdx.x] : g_M3[threadIdx.x];
    __syncthreads();
    int e = blockIdx.x * 256 + threadIdx.x;
    if (e >= EE) return;
    int s = ei[e], d = ei[EE + e], t = etype[e];
    float4 qv = *(const float4*)&g_qn[((size_t)t * NN + d) * 4];
    float4 kv = *(const float4*)&g_kn[((size_t)t * NN + s) * 4];
    const float* a = eattr + (size_t)e * FE;
    float e0 = 0.f, e1 = 0.f, e2 = 0.f, e3 = 0.f;
#pragma unroll
    for (int f4 = 0; f4 < 4; f4++) {
        float4 av = *(const float4*)(a + f4 * 4);
        const float* m = &sM[f4 * 16];
        e0 += av.x * m[0] + av.y * m[4] + av.z * m[8]  + av.w * m[12];
        e1 += av.x * m[1] + av.y * m[5] + av.z * m[9]  + av.w * m[13];
        e2 += av.x * m[2] + av.y * m[6] + av.z * m[10] + av.w * m[14];
        e3 += av.x * m[3] + av.y * m[7] + av.z * m[11] + av.w * m[15];
    }
    float a0 = qv.x + kv.x + e0; a0 = a0 > 0.f ? a0 : 0.2f * a0;
    float a1 = qv.y + kv.y + e1; a1 = a1 > 0.f ? a1 : 0.2f * a1;
    float a2 = qv.z + kv.z + e2; a2 = a2 > 0.f ? a2 : 0.2f * a2;
    float a3 = qv.w + kv.w + e3; a3 = a3 > 0.f ? a3 : 0.2f * a3;
    g_pp[g_pos[e]] = make_float4(__expf(a0), __expf(a1), __expf(a2), __expf(a3));
}

// ---------------- softmax-normalize + aggregate: warp per dst node ----------------
// Lane owns channels 4*lane..4*lane+3 (all in head lane>>3): one LDG.128 per edge.
__global__ void k_agg(const float* __restrict__ bias, float* __restrict__ out, int layer) {
    int n = (blockIdx.x * blockDim.x + threadIdx.x) >> 5;
    int lane = threadIdx.x & 31;
    if (n >= NN) return;
    int rs = g_rowstart[n], re = g_rowstart[n + 1];
    int h = lane >> 3;

    float s = 0.f;
    float4 acc = make_float4(0.f, 0.f, 0.f, 0.f);

    int e = rs;
    for (; e + 4 <= re; e += 4) {
        int r0 = g_csr32[e], r1 = g_csr32[e + 1], r2 = g_csr32[e + 2], r3 = g_csr32[e + 3];
        float4 p0 = g_pp[e], p1 = g_pp[e + 1], p2 = g_pp[e + 2], p3 = g_pp[e + 3];
        const float4* x0 = (const float4*)(g_xw + ((size_t)(r0 >> 16) * NN + (r0 & 0xFFFF)) * 128) + lane;
        const float4* x1 = (const float4*)(g_xw + ((size_t)(r1 >> 16) * NN + (r1 & 0xFFFF)) * 128) + lane;
        const float4* x2 = (const float4*)(g_xw + ((size_t)(r2 >> 16) * NN + (r2 & 0xFFFF)) * 128) + lane;
        const float4* x3 = (const float4*)(g_xw + ((size_t)(r3 >> 16) * NN + (r3 & 0xFFFF)) * 128) + lane;
        float4 v0 = *x0, v1 = *x1, v2 = *x2, v3 = *x3;
        float ph0 = h < 2 ? (h == 0 ? p0.x : p0.y) : (h == 2 ? p0.z : p0.w);
        float ph1 = h < 2 ? (h == 0 ? p1.x : p1.y) : (h == 2 ? p1.z : p1.w);
        float ph2 = h < 2 ? (h == 0 ? p2.x : p2.y) : (h == 2 ? p2.z : p2.w);
        float ph3 = h < 2 ? (h == 0 ? p3.x : p3.y) : (h == 2 ? p3.z : p3.w);
        s += (ph0 + ph1) + (ph2 + ph3);
        acc.x += ph0 * v0.x + ph1 * v1.x + ph2 * v2.x + ph3 * v3.x;
        acc.y += ph0 * v0.y + ph1 * v1.y + ph2 * v2.y + ph3 * v3.y;
        acc.z += ph0 * v0.z + ph1 * v1.z + ph2 * v2.z + ph3 * v3.z;
        acc.w += ph0 * v0.w + ph1 * v1.w + ph2 * v2.w + ph3 * v3.w;
    }
    for (; e < re; e++) {
        int r0 = g_csr32[e];
        float4 p0 = g_pp[e];
        const float4* x0 = (const float4*)(g_xw + ((size_t)(r0 >> 16) * NN + (r0 & 0xFFFF)) * 128) + lane;
        float4 v0 = *x0;
        float ph0 = h < 2 ? (h == 0 ? p0.x : p0.y) : (h == 2 ? p0.z : p0.w);
        s += ph0;
        acc.x += ph0 * v0.x; acc.y += ph0 * v0.y;
        acc.z += ph0 * v0.z; acc.w += ph0 * v0.w;
    }

    const float EPS = 1e-16f;
    float inv = 1.f / (s + EPS);
    if (layer == 1) {
        float4 b4 = *(const float4*)&bias[lane * 4];
        float v0 = acc.x * inv + b4.x;
        float v1 = acc.y * inv + b4.y;
        float v2 = acc.z * inv + b4.z;
        float v3 = acc.w * inv + b4.w;
        *(float4*)&g_h[(size_t)n * 128 + lane * 4] =
            make_float4(v0 > 0.f ? v0 : 0.f, v1 > 0.f ? v1 : 0.f,
                        v2 > 0.f ? v2 : 0.f, v3 > 0.f ? v3 : 0.f);
    } else {
        float4 v = make_float4(acc.x * inv, acc.y * inv, acc.z * inv, acc.w * inv);
#pragma unroll
        for (int off = 8; off <= 16; off <<= 1) {
            v.x += __shfl_xor_sync(0xFFFFFFFF, v.x, off);
            v.y += __shfl_xor_sync(0xFFFFFFFF, v.y, off);
            v.z += __shfl_xor_sync(0xFFFFFFFF, v.z, off);
            v.w += __shfl_xor_sync(0xFFFFFFFF, v.w, off);
        }
        if (lane < 8) {
            float4 b4 = *(const float4*)&bias[lane * 4];
            *(float4*)&out[(size_t)n * 32 + lane * 4] =
                make_float4(0.25f * v.x + b4.x, 0.25f * v.y + b4.y,
                            0.25f * v.z + b4.z, 0.25f * v.w + b4.w);
        }
    }
}

// ---------------- launch ----------------
extern "C" void kernel_launch(void* const* d_in, const int* in_sizes, int n_in,
                              void* d_out, int out_size) {
    const float* x     = (const float*)d_in[0];
    const int*   ei    = (const int*)  d_in[1];
    const float* eattr = (const float*)d_in[2];
    const int*   etype = (const int*)  d_in[3];
    const float* w1  = (const float*)d_in[4];
    const float* q1  = (const float*)d_in[5];
    const float* k1  = (const float*)d_in[6];
    const float* e1  = (const float*)d_in[7];
    const float* le1 = (const float*)d_in[8];
    const float* b1  = (const float*)d_in[9];
    const float* w3  = (const float*)d_in[10];
    const float* q3  = (const float*)d_in[11];
    const float* k3  = (const float*)d_in[12];
    const float* e3  = (const float*)d_in[13];
    const float* le3 = (const float*)d_in[14];
    const float* b3  = (const float*)d_in[15];
    float* out = (float*)d_out;

    const int EB = (EE + 255) / 256;         // 3125
    const int NB = (NN + 255) / 256;         // 196
    const int WF_B = 65536 / 256;            // 256
    const dim3 GT((NN + 127) / 128, RR);     // (391, 4)

    k_zero_deg<<<NB, 256>>>();                             // 0
    k_hist<<<EB, 256>>>(ei);                               // 1
    k_wfrag<<<WF_B, 256>>>(w1);                            // 2
    k_gemmt<<<GT, 256>>>(x, q1, k1, 1);                    // 3  <- profile target
    k_scan<<<1, 1024>>>();                                 // 4
    k_scatter<<<EB, 256>>>(ei, etype);                     // 5
    k_M<<<1, 128>>>(le1, e1, le3, e3);                     // 6
    k_p<<<EB, 256>>>(ei, etype, eattr, 1);                 // 7
    k_agg<<<(NN + 7) / 8, 256>>>(b1, out, 1);              // 8

    k_wfrag<<<WF_B, 256>>>(w3);                            // 9
    k_gemmt<<<GT, 256>>>(x, q3, k3, 2);                    // 10
    k_p<<<EB, 256>>>(ei, etype, eattr, 2);                 // 11
    k_agg<<<(NN + 7) / 8, 256>>>(b3, out, 2);              // 12
}

// round 8
// speedup vs baseline: 1.1172x; 1.1172x over previous
#include <cuda_runtime.h>
#include <cstdint>

// Problem constants
#define NN   50000
#define EE   800000
#define FE   16
#define RR   4
#define HH   4
#define CC   32
#define HC   128

#define NT   17   // n-tiles in GEMM B: 16 for W (128 cols) + 1 for folded q|k (8 cols)

// ---------------- scratch (static device globals; no allocation) ----------------
__device__ __align__(16) float g_xw[RR * NN * HC];   // per-relation projections (102.4MB)
__device__ __align__(16) float g_h[NN * HC];         // layer-1 output (relu)
__device__ __align__(16) float g_qn[RR * NN * HH];   // per-node query logits [r][n][4]
__device__ __align__(16) float g_kn[RR * NN * HH];   // per-node key logits   [r][n][4]
__device__ __align__(16) float4 g_pp[EE];            // per-edge probs, CSR-permuted
__device__ int   g_deg[NN];
__device__ int   g_rowstart[NN + 1];
__device__ int   g_cursor[NN];
__device__ int   g_csr32[EE];                        // (et<<16)|src, sorted by dst
__device__ int   g_pos[EE];                          // edge id -> csr position
__device__ float g_M1[FE * HH];
__device__ float g_M3[FE * HH];
__device__ __align__(16) float g_wqk[RR * HC * 8];   // folded (W@q | W@k): [r][f][8]
// B fragments for mma.m16n8k8 tf32: [r][phase(4)][s(4)][ntile(17)][lane(32)][2]
__device__ __align__(16) uint32_t g_wf[RR * 4 * 4 * NT * 32 * 2];

__device__ __forceinline__ uint32_t f2tf32(float f) {
    uint32_t u;
    asm("cvt.rna.tf32.f32 %0, %1;" : "=r"(u) : "f"(f));
    return u;
}

// ---------------- CSR build ----------------
__global__ void k_zero_deg() {
    int i = blockIdx.x * blockDim.x + threadIdx.x;
    if (i < NN) g_deg[i] = 0;
}

__global__ void k_hist(const int* __restrict__ ei) {
    int e = blockIdx.x * blockDim.x + threadIdx.x;
    if (e < EE) atomicAdd(&g_deg[ei[EE + e]], 1);
}

// single-block exclusive scan of g_deg -> g_rowstart / g_cursor
__global__ void k_scan() {
    __shared__ int sm[1024];
    __shared__ int s_carry;
    int tid = threadIdx.x;
    if (tid == 0) s_carry = 0;
    __syncthreads();
    const int TILES = (NN + 8191) / 8192;   // 7
    for (int tile = 0; tile < TILES; tile++) {
        int base = tile * 8192 + tid * 8;
        int v[8];
        int tsum = 0;
#pragma unroll
        for (int j = 0; j < 8; j++) {
            int idx = base + j;
            v[j] = (idx < NN) ? g_deg[idx] : 0;
            tsum += v[j];
        }
        sm[tid] = tsum;
        __syncthreads();
        for (int off = 1; off < 1024; off <<= 1) {
            int t = (tid >= off) ? sm[tid - off] : 0;
            __syncthreads();
            sm[tid] += t;
            __syncthreads();
        }
        int excl = s_carry + sm[tid] - tsum;
        int run = excl;
#pragma unroll
        for (int j = 0; j < 8; j++) {
            int idx = base + j;
            if (idx < NN) { g_rowstart[idx] = run; g_cursor[idx] = run; }
            run += v[j];
        }
        __syncthreads();
        if (tid == 0) s_carry += sm[1023];
        __syncthreads();
    }
    if (tid == 0) g_rowstart[NN] = s_carry;
}

__global__ void k_scatter(const int* __restrict__ ei, const int* __restrict__ etype) {
    int e = blockIdx.x * blockDim.x + threadIdx.x;
    if (e >= EE) return;
    int d = ei[EE + e];
    int s = ei[e];
    int t = etype[e];
    int pos = atomicAdd(&g_cursor[d], 1);
    g_csr32[pos] = (t << 16) | s;
    g_pos[e] = pos;
}

// ---------------- folded q/k: g_wqk[r][f][0:4]=W_r@q, [4:8]=W_r@k (fp32) ----------------
__global__ void k_wqk(const float* __restrict__ w, const float* __restrict__ q,
                      const float* __restrict__ k) {
    int idx = blockIdx.x * 256 + threadIdx.x;    // 4096 total
    if (idx >= RR * HC * 8) return;
    int r = idx >> 10;
    int f = (idx >> 3) & 127;
    int o = idx & 7;
    const float* vec = (o < 4) ? q : k;
    int h = o & 3;
    const float* wrow = w + (r << 14) + (f << 7);
    float s = 0.f;
#pragma unroll 8
    for (int c = 0; c < HC; c++) s += wrow[c] * vec[c * 4 + h];
    g_wqk[idx] = s;
}

// ---------------- B fragment pack (W cols 0..127 + folded q|k cols 128..135) ----------------
__global__ void k_wfrag(const float* __restrict__ w) {
    int idx = blockIdx.x * 256 + threadIdx.x;          // over RR*4*4*NT*64 = 69632
    if (idx >= RR * 4 * 4 * NT * 32 * 2) return;
    int b    = idx & 1;
    int lane = (idx >> 1) & 31;
    int rest = idx >> 6;
    int j    = rest % NT;
    rest /= NT;
    int s    = rest & 3;
    int p    = (rest >> 2) & 3;
    int r    = rest >> 4;
    int k = p * 32 + s * 8 + (b ? 4 : 0) + (lane & 3);
    int c = j * 8 + (lane >> 2);
    float val;
    if (j < 16) val = w[((size_t)r << 14) + k * 128 + c];
    else        val = g_wqk[((size_t)r * HC + k) * 8 + (c - 128)];
    g_wf[idx] = f2tf32(val);
}

// ---------------- M = le @ e  (16x4, both layers) ----------------
__global__ void k_M(const float* __restrict__ le1, const float* __restrict__ e1,
                    const float* __restrict__ le3, const float* __restrict__ e3) {
    int t = threadIdx.x;
    if (t < 64) {
        int f = t >> 2, h = t & 3;
        float s = 0.f;
        for (int c = 0; c < HC; c++) s += le1[f * HC + c] * e1[c * HH + h];
        g_M1[t] = s;
    } else if (t < 128) {
        int u = t - 64;
        int f = u >> 2, h = u & 3;
        float s = 0.f;
        for (int c = 0; c < HC; c++) s += le3[f * HC + c] * e3[c * HH + h];
        g_M3[u] = s;
    }
}

// ---------------- tensor-core GEMM: [xw | qn | kn] = X @ [W | Wq | Wk] ----------------
#define XS_STRIDE 36
__global__ void __launch_bounds__(256) k_gemmt(const float* __restrict__ xin_arg, int layer) {
    __shared__ uint32_t xs[128 * XS_STRIDE];           // 18.4 KB (tf32 bits)
    __shared__ uint32_t ws[4 * NT * 32 * 2];           // 17.4 KB per K-phase
    const float* xin = (layer == 1) ? xin_arg : g_h;
    int r = blockIdx.y;
    int i0 = blockIdx.x * 128;
    int tid = threadIdx.x;
    int lane = tid & 31, wid = tid >> 5;
    int wr = wid * 16;                                  // warp row offset

    float d[NT][4];
#pragma unroll
    for (int j = 0; j < NT; j++) {
        d[j][0] = 0.f; d[j][1] = 0.f; d[j][2] = 0.f; d[j][3] = 0.f;
    }

    const uint32_t* wsrc = g_wf + (size_t)r * (4 * 4 * NT * 64);

    for (int p = 0; p < 4; p++) {
        __syncthreads();                                // protect prev phase reads
#pragma unroll
        for (int it = 0; it < 4; it++) {
            int q = tid + it * 256;                     // float4 index
            int row = q >> 3, c4 = q & 7;
            float4 v = make_float4(0.f, 0.f, 0.f, 0.f);
            int gr = i0 + row;
            if (gr < NN) v = *(const float4*)(xin + (size_t)gr * 128 + p * 32 + c4 * 4);
            uint32_t* dst = &xs[row * XS_STRIDE + c4 * 4];
            dst[0] = f2tf32(v.x); dst[1] = f2tf32(v.y);
            dst[2] = f2tf32(v.z); dst[3] = f2tf32(v.w);
        }
        // load B fragments for this phase: 4*NT*64 = 4352 uints = 1088 uint4
        const uint4* wsp = (const uint4*)(wsrc + p * (4 * NT * 64));
#pragma unroll
        for (int it = 0; it < 5; it++) {
            int q = tid + it * 256;
            if (q < 4 * NT * 16) ((uint4*)ws)[q] = __ldg(&wsp[q]);
        }
        __syncthreads();

#pragma unroll
        for (int s = 0; s < 4; s++) {
            int arow = wr + (lane >> 2);
            int acol = s * 8 + (lane & 3);
            uint32_t a0 = xs[arow * XS_STRIDE + acol];
            uint32_t a1 = xs[(arow + 8) * XS_STRIDE + acol];
            uint32_t a2 = xs[arow * XS_STRIDE + acol + 4];
            uint32_t a3 = xs[(arow + 8) * XS_STRIDE + acol + 4];
            const uint32_t* wrow = &ws[(s * NT) * 64];
#pragma unroll
            for (int j = 0; j < NT; j++) {
                uint2 bv = *(const uint2*)&wrow[j * 64 + lane * 2];
                asm volatile(
                    "mma.sync.aligned.m16n8k8.row.col.f32.tf32.tf32.f32 "
                    "{%0,%1,%2,%3}, {%4,%5,%6,%7}, {%8,%9}, {%0,%1,%2,%3};"
                    : "+f"(d[j][0]), "+f"(d[j][1]), "+f"(d[j][2]), "+f"(d[j][3])
                    : "r"(a0), "r"(a1), "r"(a2), "r"(a3), "r"(bv.x), "r"(bv.y));
            }
        }
    }

    // store xw tile (tiles 0..15)
    int row0 = i0 + wr + (lane >> 2);
    int row1 = row0 + 8;
    float* base = g_xw + (size_t)r * NN * HC;
#pragma unroll
    for (int j = 0; j < 16; j++) {
        int col = j * 8 + (lane & 3) * 2;
        if (row0 < NN) *(float2*)&base[(size_t)row0 * 128 + col] = make_float2(d[j][0], d[j][1]);
        if (row1 < NN) *(float2*)&base[(size_t)row1 * 128 + col] = make_float2(d[j][2], d[j][3]);
    }
    // tile 16 holds qn (cols 0..3) | kn (cols 4..7) per row
    {
        int q4 = lane & 3;                               // col pair = 2*q4
        float* dst = (q4 < 2) ? g_qn : g_kn;
        int off = (q4 < 2) ? q4 * 2 : (q4 - 2) * 2;
        if (row0 < NN) *(float2*)&dst[((size_t)r * NN + row0) * 4 + off] = make_float2(d[16][0], d[16][1]);
        if (row1 < NN) *(float2*)&dst[((size_t)r * NN + row1) * 4 + off] = make_float2(d[16][2], d[16][3]);
    }
}

// ---------------- per-edge probs, written in CSR order ----------------
__global__ void k_p(const int* __restrict__ ei, const int* __restrict__ etype,
                    const float* __restrict__ eattr, int layer) {
    __shared__ float sM[64];
    if (threadIdx.x < 64) sM[threadIdx.x] = (layer == 1) ? g_M1[threadIdx.x] : g_M3[threadIdx.x];
    __syncthreads();
    int e = blockIdx.x * 256 + threadIdx.x;
    if (e >= EE) return;
    int s = ei[e], d = ei[EE + e], t = etype[e];
    float4 qv = *(const float4*)&g_qn[((size_t)t * NN + d) * 4];
    float4 kv = *(const float4*)&g_kn[((size_t)t * NN + s) * 4];
    const float* a = eattr + (size_t)e * FE;
    float e0 = 0.f, e1 = 0.f, e2 = 0.f, e3 = 0.f;
#pragma unroll
    for (int f4 = 0; f4 < 4; f4++) {
        float4 av = *(const float4*)(a + f4 * 4);
        const float* m = &sM[f4 * 16];
        e0 += av.x * m[0] + av.y * m[4] + av.z * m[8]  + av.w * m[12];
        e1 += av.x * m[1] + av.y * m[5] + av.z * m[9]  + av.w * m[13];
        e2 += av.x * m[2] + av.y * m[6] + av.z * m[10] + av.w * m[14];
        e3 += av.x * m[3] + av.y * m[7] + av.z * m[11] + av.w * m[15];
    }
    float a0 = qv.x + kv.x + e0; a0 = a0 > 0.f ? a0 : 0.2f * a0;
    float a1 = qv.y + kv.y + e1; a1 = a1 > 0.f ? a1 : 0.2f * a1;
    float a2 = qv.z + kv.z + e2; a2 = a2 > 0.f ? a2 : 0.2f * a2;
    float a3 = qv.w + kv.w + e3; a3 = a3 > 0.f ? a3 : 0.2f * a3;
    g_pp[g_pos[e]] = make_float4(__expf(a0), __expf(a1), __expf(a2), __expf(a3));
}

// ---------------- softmax-normalize + aggregate: warp per dst node ----------------
// Lane owns channels 4*lane..4*lane+3 (all in head lane>>3): one LDG.128 per edge.
__global__ void k_agg(const float* __restrict__ bias, float* __restrict__ out, int layer) {
    int n = (blockIdx.x * blockDim.x + threadIdx.x) >> 5;
    int lane = threadIdx.x & 31;
    if (n >= NN) return;
    int rs = g_rowstart[n], re = g_rowstart[n + 1];
    int h = lane >> 3;

    float s = 0.f;
    float4 acc = make_float4(0.f, 0.f, 0.f, 0.f);

    int e = rs;
    for (; e + 4 <= re; e += 4) {
        int r0 = g_csr32[e], r1 = g_csr32[e + 1], r2 = g_csr32[e + 2], r3 = g_csr32[e + 3];
        float4 p0 = g_pp[e], p1 = g_pp[e + 1], p2 = g_pp[e + 2], p3 = g_pp[e + 3];
        const float4* x0 = (const float4*)(g_xw + ((size_t)(r0 >> 16) * NN + (r0 & 0xFFFF)) * 128) + lane;
        const float4* x1 = (const float4*)(g_xw + ((size_t)(r1 >> 16) * NN + (r1 & 0xFFFF)) * 128) + lane;
        const float4* x2 = (const float4*)(g_xw + ((size_t)(r2 >> 16) * NN + (r2 & 0xFFFF)) * 128) + lane;
        const float4* x3 = (const float4*)(g_xw + ((size_t)(r3 >> 16) * NN + (r3 & 0xFFFF)) * 128) + lane;
        float4 v0 = *x0, v1 = *x1, v2 = *x2, v3 = *x3;
        float ph0 = h < 2 ? (h == 0 ? p0.x : p0.y) : (h == 2 ? p0.z : p0.w);
        float ph1 = h < 2 ? (h == 0 ? p1.x : p1.y) : (h == 2 ? p1.z : p1.w);
        float ph2 = h < 2 ? (h == 0 ? p2.x : p2.y) : (h == 2 ? p2.z : p2.w);
        float ph3 = h < 2 ? (h == 0 ? p3.x : p3.y) : (h == 2 ? p3.z : p3.w);
        s += (ph0 + ph1) + (ph2 + ph3);
        acc.x += ph0 * v0.x + ph1 * v1.x + ph2 * v2.x + ph3 * v3.x;
        acc.y += ph0 * v0.y + ph1 * v1.y + ph2 * v2.y + ph3 * v3.y;
        acc.z += ph0 * v0.z + ph1 * v1.z + ph2 * v2.z + ph3 * v3.z;
        acc.w += ph0 * v0.w + ph1 * v1.w + ph2 * v2.w + ph3 * v3.w;
    }
    for (; e < re; e++) {
        int r0 = g_csr32[e];
        float4 p0 = g_pp[e];
        const float4* x0 = (const float4*)(g_xw + ((size_t)(r0 >> 16) * NN + (r0 & 0xFFFF)) * 128) + lane;
        float4 v0 = *x0;
        float ph0 = h < 2 ? (h == 0 ? p0.x : p0.y) : (h == 2 ? p0.z : p0.w);
        s += ph0;
        acc.x += ph0 * v0.x; acc.y += ph0 * v0.y;
        acc.z += ph0 * v0.z; acc.w += ph0 * v0.w;
    }

    const float EPS = 1e-16f;
    float inv = 1.f / (s + EPS);
    if (layer == 1) {
        float4 b4 = *(const float4*)&bias[lane * 4];
        float v0 = acc.x * inv + b4.x;
        float v1 = acc.y * inv + b4.y;
        float v2 = acc.z * inv + b4.z;
        float v3 = acc.w * inv + b4.w;
        *(float4*)&g_h[(size_t)n * 128 + lane * 4] =
            make_float4(v0 > 0.f ? v0 : 0.f, v1 > 0.f ? v1 : 0.f,
                        v2 > 0.f ? v2 : 0.f, v3 > 0.f ? v3 : 0.f);
    } else {
        float4 v = make_float4(acc.x * inv, acc.y * inv, acc.z * inv, acc.w * inv);
#pragma unroll
        for (int off = 8; off <= 16; off <<= 1) {
            v.x += __shfl_xor_sync(0xFFFFFFFF, v.x, off);
            v.y += __shfl_xor_sync(0xFFFFFFFF, v.y, off);
            v.z += __shfl_xor_sync(0xFFFFFFFF, v.z, off);
            v.w += __shfl_xor_sync(0xFFFFFFFF, v.w, off);
        }
        if (lane < 8) {
            float4 b4 = *(const float4*)&bias[lane * 4];
            *(float4*)&out[(size_t)n * 32 + lane * 4] =
                make_float4(0.25f * v.x + b4.x, 0.25f * v.y + b4.y,
                            0.25f * v.z + b4.z, 0.25f * v.w + b4.w);
        }
    }
}

// ---------------- launch ----------------
extern "C" void kernel_launch(void* const* d_in, const int* in_sizes, int n_in,
                              void* d_out, int out_size) {
    const float* x     = (const float*)d_in[0];
    const int*   ei    = (const int*)  d_in[1];
    const float* eattr = (const float*)d_in[2];
    const int*   etype = (const int*)  d_in[3];
    const float* w1  = (const float*)d_in[4];
    const float* q1  = (const float*)d_in[5];
    const float* k1  = (const float*)d_in[6];
    const float* e1  = (const float*)d_in[7];
    const float* le1 = (const float*)d_in[8];
    const float* b1  = (const float*)d_in[9];
    const float* w3  = (const float*)d_in[10];
    const float* q3  = (const float*)d_in[11];
    const float* k3  = (const float*)d_in[12];
    const float* e3  = (const float*)d_in[13];
    const float* le3 = (const float*)d_in[14];
    const float* b3  = (const float*)d_in[15];
    float* out = (float*)d_out;

    const int EB = (EE + 255) / 256;         // 3125
    const int NB = (NN + 255) / 256;         // 196
    const int WF_B = (RR * 4 * 4 * NT * 64 + 255) / 256;   // 272
    const dim3 GT((NN + 127) / 128, RR);     // (391, 4)

    k_zero_deg<<<NB, 256>>>();                             // 0
    k_hist<<<EB, 256>>>(ei);                               // 1
    k_wqk<<<16, 256>>>(w1, q1, k1);                        // 2
    k_wfrag<<<WF_B, 256>>>(w1);                            // 3
    k_gemmt<<<GT, 256>>>(x, 1);                            // 4  <- profile target (-s 5 hits here-ish)
    k_scan<<<1, 1024>>>();                                 // 5
    k_scatter<<<EB, 256>>>(ei, etype);                     // 6
    k_M<<<1, 128>>>(le1, e1, le3, e3);                     // 7
    k_p<<<EB, 256>>>(ei, etype, eattr, 1);                 // 8
    k_agg<<<(NN + 7) / 8, 256>>>(b1, out, 1);              // 9

    k_wqk<<<16, 256>>>(w3, q3, k3);                        // 10
    k_wfrag<<<WF_B, 256>>>(w3);                            // 11
    k_gemmt<<<GT, 256>>>(x, 2);                            // 12
    k_p<<<EB, 256>>>(ei, etype, eattr, 2);                 // 13
    k_agg<<<(NN + 7) / 8, 256>>>(b3, out, 2);              // 14
}

// round 9
// speedup vs baseline: 1.3598x; 1.2171x over previous
#include <cuda_runtime.h>
#include <cstdint>

// Problem constants
#define NN   50000
#define EE   800000
#define FE   16
#define RR   4
#define HH   4
#define CC   32
#define HC   128

#define NT   17   // n-tiles in GEMM B: 16 for W (128 cols) + 1 for folded q|k (8 cols)
#define WFSZ (RR * 4 * 4 * NT * 32 * 2)

// ---------------- scratch (static device globals; no allocation) ----------------
__device__ __align__(16) float g_xw[RR * NN * HC];   // per-relation projections (102.4MB)
__device__ __align__(16) float g_h[NN * HC];         // layer-1 output (relu)
__device__ __align__(16) float g_qn[RR * NN * HH];   // per-node query logits [r][n][4]
__device__ __align__(16) float g_kn[RR * NN * HH];   // per-node key logits   [r][n][4]
__device__ __align__(16) float4 g_pp[EE];            // per-edge probs, CSR-permuted
__device__ int   g_deg[NN];
__device__ int   g_rowstart[NN + 1];
__device__ int   g_cursor[NN];
__device__ int   g_csr32[EE];                        // (et<<16)|src, sorted by dst
__device__ int   g_pos[EE];                          // edge id -> csr position
__device__ float g_M1[FE * HH];
__device__ float g_M3[FE * HH];
__device__ __align__(16) float g_wqk[2][RR * HC * 8];   // folded (W@q | W@k), per layer slot
// B fragments for mma.m16n8k8 tf32, double-buffered per layer slot
__device__ __align__(16) uint32_t g_wf[2][WFSZ];

__device__ __forceinline__ uint32_t f2tf32(float f) {
    uint32_t u;
    asm("cvt.rna.tf32.f32 %0, %1;" : "=r"(u) : "f"(f));
    return u;
}

// ---------------- CSR build ----------------
__global__ void k_zero_deg() {
    int i = blockIdx.x * blockDim.x + threadIdx.x;
    if (i < NN) g_deg[i] = 0;
}

__global__ void k_hist(const int* __restrict__ ei) {
    int e = blockIdx.x * blockDim.x + threadIdx.x;
    if (e < EE) atomicAdd(&g_deg[ei[EE + e]], 1);
}

// single-block exclusive scan of g_deg -> g_rowstart / g_cursor
__global__ void k_scan() {
    __shared__ int sm[1024];
    __shared__ int s_carry;
    int tid = threadIdx.x;
    if (tid == 0) s_carry = 0;
    __syncthreads();
    const int TILES = (NN + 8191) / 8192;   // 7
    for (int tile = 0; tile < TILES; tile++) {
        int base = tile * 8192 + tid * 8;
        int v[8];
        int tsum = 0;
#pragma unroll
        for (int j = 0; j < 8; j++) {
            int idx = base + j;
            v[j] = (idx < NN) ? g_deg[idx] : 0;
            tsum += v[j];
        }
        sm[tid] = tsum;
        __syncthreads();
        for (int off = 1; off < 1024; off <<= 1) {
            int t = (tid >= off) ? sm[tid - off] : 0;
            __syncthreads();
            sm[tid] += t;
            __syncthreads();
        }
        int excl = s_carry + sm[tid] - tsum;
        int run = excl;
#pragma unroll
        for (int j = 0; j < 8; j++) {
            int idx = base + j;
            if (idx < NN) { g_rowstart[idx] = run; g_cursor[idx] = run; }
            run += v[j];
        }
        __syncthreads();
        if (tid == 0) s_carry += sm[1023];
        __syncthreads();
    }
    if (tid == 0) g_rowstart[NN] = s_carry;
}

__global__ void k_scatter(const int* __restrict__ ei, const int* __restrict__ etype) {
    int e = blockIdx.x * blockDim.x + threadIdx.x;
    if (e >= EE) return;
    int d = ei[EE + e];
    int s = ei[e];
    int t = etype[e];
    int pos = atomicAdd(&g_cursor[d], 1);
    g_csr32[pos] = (t << 16) | s;
    g_pos[e] = pos;
}

// ---------------- folded q/k: g_wqk[slot][r][f][0:4]=W_r@q, [4:8]=W_r@k (fp32) ----------------
__global__ void k_wqk(const float* __restrict__ w, const float* __restrict__ q,
                      const float* __restrict__ k, int slot) {
    int idx = blockIdx.x * 256 + threadIdx.x;    // 4096 total
    if (idx >= RR * HC * 8) return;
    int r = idx >> 10;
    int f = (idx >> 3) & 127;
    int o = idx & 7;
    const float* vec = (o < 4) ? q : k;
    int h = o & 3;
    const float* wrow = w + (r << 14) + (f << 7);
    float s = 0.f;
#pragma unroll 8
    for (int c = 0; c < HC; c++) s += wrow[c] * vec[c * 4 + h];
    g_wqk[slot][idx] = s;
}

// ---------------- B fragment pack (W cols 0..127 + folded q|k cols 128..135) ----------------
__global__ void k_wfrag(const float* __restrict__ w, int slot) {
    int idx = blockIdx.x * 256 + threadIdx.x;          // over WFSZ = 69632
    if (idx >= WFSZ) return;
    int b    = idx & 1;
    int lane = (idx >> 1) & 31;
    int rest = idx >> 6;
    int j    = rest % NT;
    rest /= NT;
    int s    = rest & 3;
    int p    = (rest >> 2) & 3;
    int r    = rest >> 4;
    int k = p * 32 + s * 8 + (b ? 4 : 0) + (lane & 3);
    int c = j * 8 + (lane >> 2);
    float val;
    if (j < 16) val = w[((size_t)r << 14) + k * 128 + c];
    else        val = g_wqk[slot][((size_t)r * HC + k) * 8 + (c - 128)];
    g_wf[slot][idx] = f2tf32(val);
}

// ---------------- M = le @ e  (16x4, both layers) ----------------
__global__ void k_M(const float* __restrict__ le1, const float* __restrict__ e1,
                    const float* __restrict__ le3, const float* __restrict__ e3) {
    int t = threadIdx.x;
    if (t < 64) {
        int f = t >> 2, h = t & 3;
        float s = 0.f;
        for (int c = 0; c < HC; c++) s += le1[f * HC + c] * e1[c * HH + h];
        g_M1[t] = s;
    } else if (t < 128) {
        int u = t - 64;
        int f = u >> 2, h = u & 3;
        float s = 0.f;
        for (int c = 0; c < HC; c++) s += le3[f * HC + c] * e3[c * HH + h];
        g_M3[u] = s;
    }
}

// ---------------- tensor-core GEMM: [xw | qn | kn] = X @ [W | Wq | Wk] ----------------
#define XS_STRIDE 36
__global__ void __launch_bounds__(256) k_gemmt(const float* __restrict__ xin_arg, int layer) {
    __shared__ uint32_t xs[128 * XS_STRIDE];           // 18.4 KB (tf32 bits)
    __shared__ uint32_t ws[4 * NT * 32 * 2];           // 17.4 KB per K-phase
    const float* xin = (layer == 1) ? xin_arg : g_h;
    int slot = layer - 1;
    int r = blockIdx.y;
    int i0 = blockIdx.x * 128;
    int tid = threadIdx.x;
    int lane = tid & 31, wid = tid >> 5;
    int wr = wid * 16;                                  // warp row offset

    float d[NT][4];
#pragma unroll
    for (int j = 0; j < NT; j++) {
        d[j][0] = 0.f; d[j][1] = 0.f; d[j][2] = 0.f; d[j][3] = 0.f;
    }

    const uint32_t* wsrc = g_wf[slot] + (size_t)r * (4 * 4 * NT * 64);

    for (int p = 0; p < 4; p++) {
        __syncthreads();                                // protect prev phase reads
#pragma unroll
        for (int it = 0; it < 4; it++) {
            int q = tid + it * 256;                     // float4 index
            int row = q >> 3, c4 = q & 7;
            float4 v = make_float4(0.f, 0.f, 0.f, 0.f);
            int gr = i0 + row;
            if (gr < NN) v = *(const float4*)(xin + (size_t)gr * 128 + p * 32 + c4 * 4);
            uint32_t* dst = &xs[row * XS_STRIDE + c4 * 4];
            dst[0] = f2tf32(v.x); dst[1] = f2tf32(v.y);
            dst[2] = f2tf32(v.z); dst[3] = f2tf32(v.w);
        }
        // load B fragments for this phase: 4*NT*64 = 4352 uints = 1088 uint4
        const uint4* wsp = (const uint4*)(wsrc + p * (4 * NT * 64));
#pragma unroll
        for (int it = 0; it < 5; it++) {
            int q = tid + it * 256;
            if (q < 4 * NT * 16) ((uint4*)ws)[q] = __ldg(&wsp[q]);
        }
        __syncthreads();

#pragma unroll
        for (int s = 0; s < 4; s++) {
            int arow = wr + (lane >> 2);
            int acol = s * 8 + (lane & 3);
            uint32_t a0 = xs[arow * XS_STRIDE + acol];
            uint32_t a1 = xs[(arow + 8) * XS_STRIDE + acol];
            uint32_t a2 = xs[arow * XS_STRIDE + acol + 4];
            uint32_t a3 = xs[(arow + 8) * XS_STRIDE + acol + 4];
            const uint32_t* wrow = &ws[(s * NT) * 64];
#pragma unroll
            for (int j = 0; j < NT; j++) {
                uint2 bv = *(const uint2*)&wrow[j * 64 + lane * 2];
                asm volatile(
                    "mma.sync.aligned.m16n8k8.row.col.f32.tf32.tf32.f32 "
                    "{%0,%1,%2,%3}, {%4,%5,%6,%7}, {%8,%9}, {%0,%1,%2,%3};"
                    : "+f"(d[j][0]), "+f"(d[j][1]), "+f"(d[j][2]), "+f"(d[j][3])
                    : "r"(a0), "r"(a1), "r"(a2), "r"(a3), "r"(bv.x), "r"(bv.y));
            }
        }
    }

    // store xw tile (tiles 0..15)
    int row0 = i0 + wr + (lane >> 2);
    int row1 = row0 + 8;
    float* base = g_xw + (size_t)r * NN * HC;
#pragma unroll
    for (int j = 0; j < 16; j++) {
        int col = j * 8 + (lane & 3) * 2;
        if (row0 < NN) *(float2*)&base[(size_t)row0 * 128 + col] = make_float2(d[j][0], d[j][1]);
        if (row1 < NN) *(float2*)&base[(size_t)row1 * 128 + col] = make_float2(d[j][2], d[j][3]);
    }
    // tile 16 holds qn (cols 0..3) | kn (cols 4..7) per row
    {
        int q4 = lane & 3;                               // col pair = 2*q4
        float* dst = (q4 < 2) ? g_qn : g_kn;
        int off = (q4 < 2) ? q4 * 2 : (q4 - 2) * 2;
        if (row0 < NN) *(float2*)&dst[((size_t)r * NN + row0) * 4 + off] = make_float2(d[16][0], d[16][1]);
        if (row1 < NN) *(float2*)&dst[((size_t)r * NN + row1) * 4 + off] = make_float2(d[16][2], d[16][3]);
    }
}

// ---------------- per-edge probs, written in CSR order ----------------
__global__ void k_p(const int* __restrict__ ei, const int* __restrict__ etype,
                    const float* __restrict__ eattr, int layer) {
    __shared__ float sM[64];
    if (threadIdx.x < 64) sM[threadIdx.x] = (layer == 1) ? g_M1[threadIdx.x] : g_M3[threadIdx.x];
    __syncthreads();
    int e = blockIdx.x * 256 + threadIdx.x;
    if (e >= EE) return;
    int s = ei[e], d = ei[EE + e], t = etype[e];
    float4 qv = *(const float4*)&g_qn[((size_t)t * NN + d) * 4];
    float4 kv = *(const float4*)&g_kn[((size_t)t * NN + s) * 4];
    const float* a = eattr + (size_t)e * FE;
    float e0 = 0.f, e1 = 0.f, e2 = 0.f, e3 = 0.f;
#pragma unroll
    for (int f4 = 0; f4 < 4; f4++) {
        float4 av = *(const float4*)(a + f4 * 4);
        const float* m = &sM[f4 * 16];
        e0 += av.x * m[0] + av.y * m[4] + av.z * m[8]  + av.w * m[12];
        e1 += av.x * m[1] + av.y * m[5] + av.z * m[9]  + av.w * m[13];
        e2 += av.x * m[2] + av.y * m[6] + av.z * m[10] + av.w * m[14];
        e3 += av.x * m[3] + av.y * m[7] + av.z * m[11] + av.w * m[15];
    }
    float a0 = qv.x + kv.x + e0; a0 = a0 > 0.f ? a0 : 0.2f * a0;
    float a1 = qv.y + kv.y + e1; a1 = a1 > 0.f ? a1 : 0.2f * a1;
    float a2 = qv.z + kv.z + e2; a2 = a2 > 0.f ? a2 : 0.2f * a2;
    float a3 = qv.w + kv.w + e3; a3 = a3 > 0.f ? a3 : 0.2f * a3;
    g_pp[g_pos[e]] = make_float4(__expf(a0), __expf(a1), __expf(a2), __expf(a3));
}

// ---------------- softmax-normalize + aggregate: warp per dst node ----------------
// Lane owns channels 4*lane..4*lane+3 (all in head lane>>3): one LDG.128 per edge.
__global__ void k_agg(const float* __restrict__ bias, float* __restrict__ out, int layer) {
    int n = (blockIdx.x * blockDim.x + threadIdx.x) >> 5;
    int lane = threadIdx.x & 31;
    if (n >= NN) return;
    int rs = g_rowstart[n], re = g_rowstart[n + 1];
    int h = lane >> 3;

    float s = 0.f;
    float4 acc = make_float4(0.f, 0.f, 0.f, 0.f);

    int e = rs;
    for (; e + 4 <= re; e += 4) {
        int r0 = g_csr32[e], r1 = g_csr32[e + 1], r2 = g_csr32[e + 2], r3 = g_csr32[e + 3];
        float4 p0 = g_pp[e], p1 = g_pp[e + 1], p2 = g_pp[e + 2], p3 = g_pp[e + 3];
        const float4* x0 = (const float4*)(g_xw + ((size_t)(r0 >> 16) * NN + (r0 & 0xFFFF)) * 128) + lane;
        const float4* x1 = (const float4*)(g_xw + ((size_t)(r1 >> 16) * NN + (r1 & 0xFFFF)) * 128) + lane;
        const float4* x2 = (const float4*)(g_xw + ((size_t)(r2 >> 16) * NN + (r2 & 0xFFFF)) * 128) + lane;
        const float4* x3 = (const float4*)(g_xw + ((size_t)(r3 >> 16) * NN + (r3 & 0xFFFF)) * 128) + lane;
        float4 v0 = *x0, v1 = *x1, v2 = *x2, v3 = *x3;
        float ph0 = h < 2 ? (h == 0 ? p0.x : p0.y) : (h == 2 ? p0.z : p0.w);
        float ph1 = h < 2 ? (h == 0 ? p1.x : p1.y) : (h == 2 ? p1.z : p1.w);
        float ph2 = h < 2 ? (h == 0 ? p2.x : p2.y) : (h == 2 ? p2.z : p2.w);
        float ph3 = h < 2 ? (h == 0 ? p3.x : p3.y) : (h == 2 ? p3.z : p3.w);
        s += (ph0 + ph1) + (ph2 + ph3);
        acc.x += ph0 * v0.x + ph1 * v1.x + ph2 * v2.x + ph3 * v3.x;
        acc.y += ph0 * v0.y + ph1 * v1.y + ph2 * v2.y + ph3 * v3.y;
        acc.z += ph0 * v0.z + ph1 * v1.z + ph2 * v2.z + ph3 * v3.z;
        acc.w += ph0 * v0.w + ph1 * v1.w + ph2 * v2.w + ph3 * v3.w;
    }
    for (; e < re; e++) {
        int r0 = g_csr32[e];
        float4 p0 = g_pp[e];
        const float4* x0 = (const float4*)(g_xw + ((size_t)(r0 >> 16) * NN + (r0 & 0xFFFF)) * 128) + lane;
        float4 v0 = *x0;
        float ph0 = h < 2 ? (h == 0 ? p0.x : p0.y) : (h == 2 ? p0.z : p0.w);
        s += ph0;
        acc.x += ph0 * v0.x; acc.y += ph0 * v0.y;
        acc.z += ph0 * v0.z; acc.w += ph0 * v0.w;
    }

    const float EPS = 1e-16f;
    float inv = 1.f / (s + EPS);
    if (layer == 1) {
        float4 b4 = *(const float4*)&bias[lane * 4];
        float v0 = acc.x * inv + b4.x;
        float v1 = acc.y * inv + b4.y;
        float v2 = acc.z * inv + b4.z;
        float v3 = acc.w * inv + b4.w;
        *(float4*)&g_h[(size_t)n * 128 + lane * 4] =
            make_float4(v0 > 0.f ? v0 : 0.f, v1 > 0.f ? v1 : 0.f,
                        v2 > 0.f ? v2 : 0.f, v3 > 0.f ? v3 : 0.f);
    } else {
        float4 v = make_float4(acc.x * inv, acc.y * inv, acc.z * inv, acc.w * inv);
#pragma unroll
        for (int off = 8; off <= 16; off <<= 1) {
            v.x += __shfl_xor_sync(0xFFFFFFFF, v.x, off);
            v.y += __shfl_xor_sync(0xFFFFFFFF, v.y, off);
            v.z += __shfl_xor_sync(0xFFFFFFFF, v.z, off);
            v.w += __shfl_xor_sync(0xFFFFFFFF, v.w, off);
        }
        if (lane < 8) {
            float4 b4 = *(const float4*)&bias[lane * 4];
            *(float4*)&out[(size_t)n * 32 + lane * 4] =
                make_float4(0.25f * v.x + b4.x, 0.25f * v.y + b4.y,
                            0.25f * v.z + b4.z, 0.25f * v.w + b4.w);
        }
    }
}

// ---------------- launch (fork/join over 3 streams; graph-capture safe) ----------------
extern "C" void kernel_launch(void* const* d_in, const int* in_sizes, int n_in,
                              void* d_out, int out_size) {
    const float* x     = (const float*)d_in[0];
    const int*   ei    = (const int*)  d_in[1];
    const float* eattr = (const float*)d_in[2];
    const int*   etype = (const int*)  d_in[3];
    const float* w1  = (const float*)d_in[4];
    const float* q1  = (const float*)d_in[5];
    const float* k1  = (const float*)d_in[6];
    const float* e1  = (const float*)d_in[7];
    const float* le1 = (const float*)d_in[8];
    const float* b1  = (const float*)d_in[9];
    const float* w3  = (const float*)d_in[10];
    const float* q3  = (const float*)d_in[11];
    const float* k3  = (const float*)d_in[12];
    const float* e3  = (const float*)d_in[13];
    const float* le3 = (const float*)d_in[14];
    const float* b3  = (const float*)d_in[15];
    float* out = (float*)d_out;

    const int EB = (EE + 255) / 256;         // 3125
    const int NB = (NN + 255) / 256;         // 196
    const int WF_B = (WFSZ + 255) / 256;     // 272
    const dim3 GT((NN + 127) / 128, RR);     // (391, 4)
    const int NAGG = (NN + 7) / 8;

    // lazily-created side streams/events (first call is the uncaptured
    // correctness run, so creation happens outside graph capture)
    static cudaStream_t s2 = nullptr, s3 = nullptr;
    static cudaEvent_t evRoot = nullptr, evCSR = nullptr, evW3 = nullptr;
    if (!s2) {
        cudaStreamCreateWithFlags(&s2, cudaStreamNonBlocking);
        cudaStreamCreateWithFlags(&s3, cudaStreamNonBlocking);
        cudaEventCreateWithFlags(&evRoot, cudaEventDisableTiming);
        cudaEventCreateWithFlags(&evCSR, cudaEventDisableTiming);
        cudaEventCreateWithFlags(&evW3, cudaEventDisableTiming);
    }

    // fork
    cudaEventRecord(evRoot, 0);
    cudaStreamWaitEvent(s2, evRoot, 0);
    cudaStreamWaitEvent(s3, evRoot, 0);

    // s2: CSR build chain + M (independent of GEMMs)
    k_zero_deg<<<NB, 256, 0, s2>>>();
    k_hist<<<EB, 256, 0, s2>>>(ei);
    k_scan<<<1, 1024, 0, s2>>>();
    k_scatter<<<EB, 256, 0, s2>>>(ei, etype);
    k_M<<<1, 128, 0, s2>>>(le1, e1, le3, e3);
    cudaEventRecord(evCSR, s2);

    // s3: layer-2 weight prep (slot 1)
    k_wqk<<<16, 256, 0, s3>>>(w3, q3, k3, 1);
    k_wfrag<<<WF_B, 256, 0, s3>>>(w3, 1);
    cudaEventRecord(evW3, s3);

    // stream 0: critical path
    k_wqk<<<16, 256>>>(w1, q1, k1, 0);
    k_wfrag<<<WF_B, 256>>>(w1, 0);
    k_gemmt<<<GT, 256>>>(x, 1);
    cudaStreamWaitEvent(0, evCSR, 0);                 // join CSR + M
    k_p<<<EB, 256>>>(ei, etype, eattr, 1);
    k_agg<<<NAGG, 256>>>(b1, out, 1);
    cudaStreamWaitEvent(0, evW3, 0);                  // join layer-2 weights
    k_gemmt<<<GT, 256>>>(x, 2);
    k_p<<<EB, 256>>>(ei, etype, eattr, 2);
    k_agg<<<NAGG, 256>>>(b3, out, 2);
}